// round 6
// baseline (speedup 1.0000x reference)
#include <cuda_runtime.h>
#include <cstdint>

#define SEQ   1000
#define IDIM  900
#define HDIM  4096
#define WOLD  (HDIM + IDIM + 1)   // 4997, W_out row stride
#define NBLK  148
#define TPB   512
#define CACHE_ROWS 13
#define LOOP_SMEM ((CACHE_ROWS * HDIM + HDIM) * sizeof(float))   // 229376 B

// ---------------- scratch (static device globals; no allocation) ----------------
__device__ float g_U[SEQ * HDIM];   // W_ih @ inp[t]   (t-major)
__device__ float g_P[SEQ * IDIM];   // bias + input part of readout
__device__ int   g_bar;             // monotonic arrival counter

__device__ __forceinline__ int ld_acq(const int* p) {
    int v;
    asm volatile("ld.acquire.gpu.b32 %0, [%1];" : "=r"(v) : "l"(p) : "memory");
    return v;
}
// release-ordered arrival: orders all prior writes (states STGs) before the add
__device__ __forceinline__ void arrive_release(int* p) {
    asm volatile("red.release.gpu.global.add.s32 [%0], 1;" :: "l"(p) : "memory");
}

__global__ void reset_kernel() {
    if (threadIdx.x == 0) g_bar = 0;
}

// ---------------- persistent recurrence kernel ----------------
// s_{t} = tanh(U[t] + W_hh @ s_{t-1});  states[t] = s_t
// 148 blocks (1/SM), 512 threads. Warp i (i=0..13) owns row i (SMEM-cached if
// i<13) and row i+14 (streamed from L2 with 16 LDG.128 batched in registers,
// hidden under the cached row's SMEM FMAs). Warp 15 is the barrier poller.
__global__ __launch_bounds__(TPB, 1) void esn_loop_kernel(
    const float* __restrict__ W_hh,
    const float* __restrict__ s0,
    float* __restrict__ states)
{
    extern __shared__ float sh[];
    float* w_sh = sh;                      // CACHE_ROWS * HDIM
    float* s_sh = sh + CACHE_ROWS * HDIM;  // HDIM

    const int bid  = blockIdx.x;
    const int tid  = threadIdx.x;
    const int warp = tid >> 5;
    const int lane = tid & 31;

    // 4096 = 148*27 + 100 -> blocks 0..99 get 28 rows, 100..147 get 27
    const int base  = bid * 27 + (bid < 100 ? bid : 100);
    const int nrows = (bid < 100) ? 28 : 27;

    // prologue: cache first CACHE_ROWS rows of this block's slice in SMEM
    {
        const float4* wsrc = (const float4*)(W_hh + (size_t)base * HDIM);
        float4* wdst = (float4*)w_sh;
        for (int i = tid; i < CACHE_ROWS * (HDIM / 4); i += TPB) wdst[i] = wsrc[i];
    }

    const float* s_src = s0;
    const int rA = warp;            // cached row (if warp < 13)
    const int rB = warp + 14;       // streamed row
    const bool isComp  = (warp < 14);
    const bool hasB    = isComp && (rB < nrows);
    const bool Acached = (rA < CACHE_ROWS);
    const float4* wAs = (const float4*)(w_sh + rA * HDIM);
    const float4* wAg = (const float4*)(W_hh + (size_t)(base + rA) * HDIM);
    const float4* wBg = (const float4*)(W_hh + (size_t)(base + rB) * HDIM);

    for (int t = 0; t < SEQ; ++t) {
        // stage current state vector into SMEM (1024 float4, 512 threads)
        {
            const float4* src = (const float4*)s_src;
            float4* dst = (float4*)s_sh;
            float4 v0 = src[tid];
            float4 v1 = src[tid + TPB];
            dst[tid] = v0;
            dst[tid + TPB] = v1;
        }
        __syncthreads();

        if (isComp) {
            const float4* sv = (const float4*)s_sh;
            float a0 = 0.f, a1 = 0.f, b0 = 0.f, b1 = 0.f;

            #pragma unroll
            for (int h = 0; h < 2; ++h) {
                // batch 16 streamed LDG.128 (8KB in flight per warp)
                float4 wb[16];
                if (hasB) {
                    #pragma unroll
                    for (int j = 0; j < 16; ++j)
                        wb[j] = wBg[lane + (h * 16 + j) * 32];
                }
                if (Acached) {
                    #pragma unroll
                    for (int j = 0; j < 16; ++j) {
                        const int idx = lane + (h * 16 + j) * 32;
                        float4 s = sv[idx];
                        float4 a = wAs[idx];
                        a0 = fmaf(a.x, s.x, a0); a1 = fmaf(a.y, s.y, a1);
                        a0 = fmaf(a.z, s.z, a0); a1 = fmaf(a.w, s.w, a1);
                        if (hasB) {
                            b0 = fmaf(wb[j].x, s.x, b0); b1 = fmaf(wb[j].y, s.y, b1);
                            b0 = fmaf(wb[j].z, s.z, b0); b1 = fmaf(wb[j].w, s.w, b1);
                        }
                    }
                } else {  // warp 13: row A also streams from L2
                    #pragma unroll
                    for (int j = 0; j < 16; ++j) {
                        const int idx = lane + (h * 16 + j) * 32;
                        float4 s = sv[idx];
                        float4 a = wAg[idx];
                        a0 = fmaf(a.x, s.x, a0); a1 = fmaf(a.y, s.y, a1);
                        a0 = fmaf(a.z, s.z, a0); a1 = fmaf(a.w, s.w, a1);
                        if (hasB) {
                            b0 = fmaf(wb[j].x, s.x, b0); b1 = fmaf(wb[j].y, s.y, b1);
                            b0 = fmaf(wb[j].z, s.z, b0); b1 = fmaf(wb[j].w, s.w, b1);
                        }
                    }
                }
            }
            float accA = a0 + a1;
            float accB = b0 + b1;

            #pragma unroll
            for (int off = 16; off; off >>= 1) {
                accA += __shfl_xor_sync(0xffffffffu, accA, off);
                accB += __shfl_xor_sync(0xffffffffu, accB, off);
            }
            if (lane == 0) {
                const size_t o = (size_t)t * HDIM + base;
                states[o + rA] = tanhf(accA + g_U[o + rA]);
                if (hasB) states[o + rB] = tanhf(accB + g_U[o + rB]);
            }
        }

        __syncthreads();   // all states STGs of this step issued

        if (t < SEQ - 1) {
            if (tid == 0) arrive_release(&g_bar);   // release: orders the STGs
            if (warp == 15) {                       // dedicated poller warp
                const int target = (t + 1) * NBLK;
                while (ld_acq(&g_bar) < target) { }
            }
            __syncthreads();   // barrier passed; also protects s_sh reuse
        }

        s_src = states + (size_t)t * HDIM;
    }
}

// ---------------- fp32 GEMM: C[n][m] = (bias[m]) + (Cadd[n][m]) + sum_k A[m][k]*B[n][k]
// A: M x K row stride lda (scalar loads — may be unaligned base / odd lda)
// B: N x K row stride ldb (float4 when aligned)
// 256 threads, BMxBN tile, BK=8, (BM/16)x(BN/16) microtile per thread.
template<int BM, int BN>
__global__ __launch_bounds__(256) void gemm_nt(
    const float* __restrict__ A, int lda,
    const float* __restrict__ B, int ldb,
    float* __restrict__ C, int ldc,
    const float* __restrict__ Cadd,
    const float* __restrict__ bias, int bias_stride,
    int M, int N, int K)
{
    constexpr int BK = 8;
    constexpr int TM = BM / 16;
    constexpr int TN = BN / 16;
    __shared__ float As[BK][BM + 4];
    __shared__ float Bs[BK][BN + 4];

    const int tid = threadIdx.x;
    const int tx = tid & 15;
    const int ty = tid >> 4;
    const int m0 = blockIdx.x * BM;
    const int n0 = blockIdx.y * BN;

    const bool b_vec = ((reinterpret_cast<uintptr_t>(B) & 15) == 0) && ((ldb & 3) == 0);

    float acc[TM][TN];
    #pragma unroll
    for (int i = 0; i < TM; ++i)
        #pragma unroll
        for (int j = 0; j < TN; ++j) acc[i][j] = 0.f;

    for (int kt = 0; kt < K; kt += BK) {
        // ---- load A tile (BM x 8) transposed into As, scalar loads ----
        #pragma unroll
        for (int i = tid; i < BM * 2; i += 256) {
            int m = i >> 1;
            int kq = (i & 1) * 4;
            int gm = m0 + m;
            float v0 = 0.f, v1 = 0.f, v2 = 0.f, v3 = 0.f;
            if (gm < M) {
                const float* p = A + (size_t)gm * lda + (kt + kq);
                int rem = K - (kt + kq);
                if (rem > 0) v0 = p[0];
                if (rem > 1) v1 = p[1];
                if (rem > 2) v2 = p[2];
                if (rem > 3) v3 = p[3];
            }
            As[kq + 0][m] = v0; As[kq + 1][m] = v1;
            As[kq + 2][m] = v2; As[kq + 3][m] = v3;
        }
        // ---- load B tile (BN x 8) transposed into Bs ----
        #pragma unroll
        for (int i = tid; i < BN * 2; i += 256) {
            int n = i >> 1;
            int kq = (i & 1) * 4;
            int gn = n0 + n;
            int gk = kt + kq;
            float v0 = 0.f, v1 = 0.f, v2 = 0.f, v3 = 0.f;
            if (gn < N) {
                const float* p = B + (size_t)gn * ldb + gk;
                int rem = K - gk;
                if (b_vec && rem >= 4) {
                    float4 v = *(const float4*)p;
                    v0 = v.x; v1 = v.y; v2 = v.z; v3 = v.w;
                } else {
                    if (rem > 0) v0 = p[0];
                    if (rem > 1) v1 = p[1];
                    if (rem > 2) v2 = p[2];
                    if (rem > 3) v3 = p[3];
                }
            }
            Bs[kq + 0][n] = v0; Bs[kq + 1][n] = v1;
            Bs[kq + 2][n] = v2; Bs[kq + 3][n] = v3;
        }
        __syncthreads();

        #pragma unroll
        for (int kk = 0; kk < BK; ++kk) {
            float a[TM], b[TN];
            #pragma unroll
            for (int i = 0; i < TM; ++i) a[i] = As[kk][ty * TM + i];
            #pragma unroll
            for (int j = 0; j < TN; ++j) b[j] = Bs[kk][tx * TN + j];
            #pragma unroll
            for (int i = 0; i < TM; ++i)
                #pragma unroll
                for (int j = 0; j < TN; ++j)
                    acc[i][j] = fmaf(a[i], b[j], acc[i][j]);
        }
        __syncthreads();
    }

    // ---- epilogue ----
    #pragma unroll
    for (int i = 0; i < TM; ++i) {
        int gm = m0 + ty * TM + i;
        if (gm >= M) continue;
        float bv = bias ? bias[(size_t)gm * bias_stride] : 0.f;
        #pragma unroll
        for (int j = 0; j < TN; ++j) {
            int gn = n0 + tx * TN + j;
            if (gn >= N) continue;
            float v = acc[i][j] + bv;
            if (Cadd) v += Cadd[(size_t)gn * ldc + gm];
            C[(size_t)gn * ldc + gm] = v;
        }
    }
}

// ---------------- launch ----------------
extern "C" void kernel_launch(void* const* d_in, const int* in_sizes, int n_in,
                              void* d_out, int out_size)
{
    const float* inputs = (const float*)d_in[0];  // (1000,1,900)
    const float* state0 = (const float*)d_in[1];  // (1,4096)
    const float* W_ih   = (const float*)d_in[2];  // (4096,900)
    const float* W_hh   = (const float*)d_in[3];  // (4096,4096)
    const float* W_out  = (const float*)d_in[4];  // (900,4997)

    float* out    = (float*)d_out;                // outputs: SEQ*IDIM
    float* states = out + (size_t)SEQ * IDIM;     // states : SEQ*HDIM

    float *U = nullptr, *P = nullptr;
    cudaGetSymbolAddress((void**)&U, g_U);
    cudaGetSymbolAddress((void**)&P, g_P);

    cudaFuncSetAttribute(esn_loop_kernel,
                         cudaFuncAttributeMaxDynamicSharedMemorySize, (int)LOOP_SMEM);

    reset_kernel<<<1, 32>>>();

    // U[t][h] = W_ih[h,:] . inp[t,:]            M=4096 N=1000 K=900
    gemm_nt<128, 128><<<dim3(HDIM / 128, (SEQ + 127) / 128), 256>>>(
        W_ih, IDIM, inputs, IDIM, U, HDIM,
        nullptr, nullptr, 0, HDIM, SEQ, IDIM);

    // P[t][i] = W_out[i][0] + W_out[i,1:901] . inp[t,:]   M=900 N=1000 K=900
    gemm_nt<64, 128><<<dim3((IDIM + 63) / 64, (SEQ + 127) / 128), 256>>>(
        W_out + 1, WOLD, inputs, IDIM, P, IDIM,
        nullptr, W_out, WOLD, IDIM, SEQ, IDIM);

    // sequential recurrence: states[t] = tanh(U[t] + W_hh @ states[t-1])
    esn_loop_kernel<<<NBLK, TPB, LOOP_SMEM>>>(W_hh, state0, states);

    // out[t][i] = P[t][i] + W_out[i,901:] . states[t,:]   M=900 N=1000 K=4096
    gemm_nt<64, 128><<<dim3((IDIM + 63) / 64, (SEQ + 127) / 128), 256>>>(
        W_out + 1 + IDIM, WOLD, states, HDIM, out, IDIM,
        P, nullptr, 0, IDIM, SEQ, HDIM);
}

// round 7
// speedup vs baseline: 1.0337x; 1.0337x over previous
#include <cuda_runtime.h>
#include <cstdint>

#define SEQ   1000
#define IDIM  900
#define HDIM  4096
#define WOLD  (HDIM + IDIM + 1)   // 4997, W_out row stride
#define NBLK  148
#define TPB   512
#define CACHE_ROWS 13
#define LOOP_SMEM ((CACHE_ROWS * HDIM + HDIM) * sizeof(float))   // 229376 B

// ---------------- scratch (static device globals; no allocation) ----------------
__device__ float g_U[SEQ * HDIM];   // W_ih @ inp[t]   (t-major)
__device__ float g_P[SEQ * IDIM];   // bias + input part of readout
__device__ int   g_bar;             // monotonic arrival counter

__device__ __forceinline__ int ld_acq(const int* p) {
    int v;
    asm volatile("ld.acquire.gpu.b32 %0, [%1];" : "=r"(v) : "l"(p) : "memory");
    return v;
}
// release-ordered arrival: orders all prior writes (states STGs) before the add
__device__ __forceinline__ void arrive_release(int* p) {
    asm volatile("red.release.gpu.global.add.s32 [%0], 1;" :: "l"(p) : "memory");
}

__global__ void reset_kernel() {
    if (threadIdx.x == 0) g_bar = 0;
}

// ---------------- persistent recurrence kernel ----------------
// s_{t} = tanh(U[t] + W_hh @ s_{t-1});  states[t] = s_t
// 148 blocks (1/SM), 512 threads. Warp i (i=0..13) owns:
//   rA = i     : SMEM-cached row (i<13), warp 13 streams its rA from L2
//   rB = i+14  : first half (16 float4/lane) PERSISTENTLY cached in registers,
//                second half streamed from L2 in two 8-deep batches.
// Step-invariant W_hh bytes from L2 drop ~2x vs refetching whole rows.
// Warp 15 is the grid-barrier poller (single monotonic atomic counter).
__global__ __launch_bounds__(TPB, 1) void esn_loop_kernel(
    const float* __restrict__ W_hh,
    const float* __restrict__ s0,
    float* __restrict__ states)
{
    extern __shared__ float sh[];
    float* w_sh = sh;                      // CACHE_ROWS * HDIM
    float* s_sh = sh + CACHE_ROWS * HDIM;  // HDIM

    const int bid  = blockIdx.x;
    const int tid  = threadIdx.x;
    const int warp = tid >> 5;
    const int lane = tid & 31;

    // 4096 = 148*27 + 100 -> blocks 0..99 get 28 rows, 100..147 get 27
    const int base  = bid * 27 + (bid < 100 ? bid : 100);
    const int nrows = (bid < 100) ? 28 : 27;

    // prologue: cache first CACHE_ROWS rows of this block's slice in SMEM
    {
        const float4* wsrc = (const float4*)(W_hh + (size_t)base * HDIM);
        float4* wdst = (float4*)w_sh;
        for (int i = tid; i < CACHE_ROWS * (HDIM / 4); i += TPB) wdst[i] = wsrc[i];
    }

    const int rA = warp;            // SMEM row (warps 0..12); warp 13 streams
    const int rB = warp + 14;       // half-register-cached row
    const bool isComp  = (warp < 14);
    const bool hasB    = isComp && (rB < nrows);
    const bool Acached = (rA < CACHE_ROWS);
    const float4* wAs = (const float4*)(w_sh + rA * HDIM);
    const float4* wAg = (const float4*)(W_hh + (size_t)(base + rA) * HDIM);
    const float4* wBg = (const float4*)(W_hh + (size_t)(base + rB) * HDIM);

    // persistent register cache: first half of row rB (j = 0..15)
    float4 wc[16];
    if (hasB) {
        #pragma unroll
        for (int j = 0; j < 16; ++j) wc[j] = wBg[lane + j * 32];
    }

    const float* s_src = s0;

    for (int t = 0; t < SEQ; ++t) {
        // stage current state vector into SMEM (1024 float4, 512 threads)
        {
            const float4* src = (const float4*)s_src;
            float4* dst = (float4*)s_sh;
            float4 v0 = src[tid];
            float4 v1 = src[tid + TPB];
            dst[tid] = v0;
            dst[tid + TPB] = v1;
        }
        __syncthreads();

        if (isComp) {
            const float4* sv = (const float4*)s_sh;
            float a0 = 0.f, a1 = 0.f, b0 = 0.f, b1 = 0.f;

            if (Acached) {   // warps 0..12
                // issue streamed batch 1 (rB second half, j=16..23) up front
                float4 wb[8];
                if (hasB) {
                    #pragma unroll
                    for (int j = 0; j < 8; ++j) wb[j] = wBg[lane + (16 + j) * 32];
                }
                // cached work: rA from SMEM + rB first half from registers
                #pragma unroll
                for (int j = 0; j < 16; ++j) {
                    const int idx = lane + j * 32;
                    float4 s = sv[idx];
                    float4 a = wAs[idx];
                    a0 = fmaf(a.x, s.x, a0); a1 = fmaf(a.y, s.y, a1);
                    a0 = fmaf(a.z, s.z, a0); a1 = fmaf(a.w, s.w, a1);
                    if (hasB) {
                        float4 b = wc[j];
                        b0 = fmaf(b.x, s.x, b0); b1 = fmaf(b.y, s.y, b1);
                        b0 = fmaf(b.z, s.z, b0); b1 = fmaf(b.w, s.w, b1);
                    }
                }
                // consume batch 1 (j=16..23)
                #pragma unroll
                for (int j = 0; j < 8; ++j) {
                    const int idx = lane + (16 + j) * 32;
                    float4 s = sv[idx];
                    float4 a = wAs[idx];
                    a0 = fmaf(a.x, s.x, a0); a1 = fmaf(a.y, s.y, a1);
                    a0 = fmaf(a.z, s.z, a0); a1 = fmaf(a.w, s.w, a1);
                    if (hasB) {
                        b0 = fmaf(wb[j].x, s.x, b0); b1 = fmaf(wb[j].y, s.y, b1);
                        b0 = fmaf(wb[j].z, s.z, b0); b1 = fmaf(wb[j].w, s.w, b1);
                    }
                }
                // issue + consume batch 2 (j=24..31)
                if (hasB) {
                    #pragma unroll
                    for (int j = 0; j < 8; ++j) wb[j] = wBg[lane + (24 + j) * 32];
                }
                #pragma unroll
                for (int j = 0; j < 8; ++j) {
                    const int idx = lane + (24 + j) * 32;
                    float4 s = sv[idx];
                    float4 a = wAs[idx];
                    a0 = fmaf(a.x, s.x, a0); a1 = fmaf(a.y, s.y, a1);
                    a0 = fmaf(a.z, s.z, a0); a1 = fmaf(a.w, s.w, a1);
                    if (hasB) {
                        b0 = fmaf(wb[j].x, s.x, b0); b1 = fmaf(wb[j].y, s.y, b1);
                        b0 = fmaf(wb[j].z, s.z, b0); b1 = fmaf(wb[j].w, s.w, b1);
                    }
                }
            } else {   // warp 13: rA streamed from L2 in 8 batches of 4
                #pragma unroll
                for (int h = 0; h < 8; ++h) {
                    float4 wa[4];
                    #pragma unroll
                    for (int j = 0; j < 4; ++j) wa[j] = wAg[lane + (h * 4 + j) * 32];
                    float4 wbv[4];
                    if (hasB && h >= 4) {
                        #pragma unroll
                        for (int j = 0; j < 4; ++j) wbv[j] = wBg[lane + (h * 4 + j) * 32];
                    }
                    #pragma unroll
                    for (int j = 0; j < 4; ++j) {
                        const int jj = h * 4 + j;
                        const int idx = lane + jj * 32;
                        float4 s = sv[idx];
                        float4 a = wa[j];
                        a0 = fmaf(a.x, s.x, a0); a1 = fmaf(a.y, s.y, a1);
                        a0 = fmaf(a.z, s.z, a0); a1 = fmaf(a.w, s.w, a1);
                        if (hasB) {
                            float4 b = (jj < 16) ? wc[jj] : wbv[j];
                            b0 = fmaf(b.x, s.x, b0); b1 = fmaf(b.y, s.y, b1);
                            b0 = fmaf(b.z, s.z, b0); b1 = fmaf(b.w, s.w, b1);
                        }
                    }
                }
            }

            float accA = a0 + a1;
            float accB = b0 + b1;
            #pragma unroll
            for (int off = 16; off; off >>= 1) {
                accA += __shfl_xor_sync(0xffffffffu, accA, off);
                accB += __shfl_xor_sync(0xffffffffu, accB, off);
            }
            if (lane == 0) {
                const size_t o = (size_t)t * HDIM + base;
                states[o + rA] = tanhf(accA + g_U[o + rA]);
                if (hasB) states[o + rB] = tanhf(accB + g_U[o + rB]);
            }
        }

        __syncthreads();   // all states STGs of this step issued

        if (t < SEQ - 1) {
            if (tid == 0) arrive_release(&g_bar);   // release: orders the STGs
            if (warp == 15) {                       // dedicated poller warp
                const int target = (t + 1) * NBLK;
                while (ld_acq(&g_bar) < target) { }
            }
            __syncthreads();   // barrier passed; also protects s_sh reuse
        }

        s_src = states + (size_t)t * HDIM;
    }
}

// ---------------- fp32 GEMM: C[n][m] = (bias[m]) + (Cadd[n][m]) + sum_k A[m][k]*B[n][k]
// A: M x K row stride lda (scalar loads — may be unaligned base / odd lda)
// B: N x K row stride ldb (float4 when aligned)
// 256 threads, BMxBN tile, BK=8, (BM/16)x(BN/16) microtile per thread.
template<int BM, int BN>
__global__ __launch_bounds__(256) void gemm_nt(
    const float* __restrict__ A, int lda,
    const float* __restrict__ B, int ldb,
    float* __restrict__ C, int ldc,
    const float* __restrict__ Cadd,
    const float* __restrict__ bias, int bias_stride,
    int M, int N, int K)
{
    constexpr int BK = 8;
    constexpr int TM = BM / 16;
    constexpr int TN = BN / 16;
    __shared__ float As[BK][BM + 4];
    __shared__ float Bs[BK][BN + 4];

    const int tid = threadIdx.x;
    const int tx = tid & 15;
    const int ty = tid >> 4;
    const int m0 = blockIdx.x * BM;
    const int n0 = blockIdx.y * BN;

    const bool b_vec = ((reinterpret_cast<uintptr_t>(B) & 15) == 0) && ((ldb & 3) == 0);

    float acc[TM][TN];
    #pragma unroll
    for (int i = 0; i < TM; ++i)
        #pragma unroll
        for (int j = 0; j < TN; ++j) acc[i][j] = 0.f;

    for (int kt = 0; kt < K; kt += BK) {
        // ---- load A tile (BM x 8) transposed into As, scalar loads ----
        #pragma unroll
        for (int i = tid; i < BM * 2; i += 256) {
            int m = i >> 1;
            int kq = (i & 1) * 4;
            int gm = m0 + m;
            float v0 = 0.f, v1 = 0.f, v2 = 0.f, v3 = 0.f;
            if (gm < M) {
                const float* p = A + (size_t)gm * lda + (kt + kq);
                int rem = K - (kt + kq);
                if (rem > 0) v0 = p[0];
                if (rem > 1) v1 = p[1];
                if (rem > 2) v2 = p[2];
                if (rem > 3) v3 = p[3];
            }
            As[kq + 0][m] = v0; As[kq + 1][m] = v1;
            As[kq + 2][m] = v2; As[kq + 3][m] = v3;
        }
        // ---- load B tile (BN x 8) transposed into Bs ----
        #pragma unroll
        for (int i = tid; i < BN * 2; i += 256) {
            int n = i >> 1;
            int kq = (i & 1) * 4;
            int gn = n0 + n;
            int gk = kt + kq;
            float v0 = 0.f, v1 = 0.f, v2 = 0.f, v3 = 0.f;
            if (gn < N) {
                const float* p = B + (size_t)gn * ldb + gk;
                int rem = K - gk;
                if (b_vec && rem >= 4) {
                    float4 v = *(const float4*)p;
                    v0 = v.x; v1 = v.y; v2 = v.z; v3 = v.w;
                } else {
                    if (rem > 0) v0 = p[0];
                    if (rem > 1) v1 = p[1];
                    if (rem > 2) v2 = p[2];
                    if (rem > 3) v3 = p[3];
                }
            }
            Bs[kq + 0][n] = v0; Bs[kq + 1][n] = v1;
            Bs[kq + 2][n] = v2; Bs[kq + 3][n] = v3;
        }
        __syncthreads();

        #pragma unroll
        for (int kk = 0; kk < BK; ++kk) {
            float a[TM], b[TN];
            #pragma unroll
            for (int i = 0; i < TM; ++i) a[i] = As[kk][ty * TM + i];
            #pragma unroll
            for (int j = 0; j < TN; ++j) b[j] = Bs[kk][tx * TN + j];
            #pragma unroll
            for (int i = 0; i < TM; ++i)
                #pragma unroll
                for (int j = 0; j < TN; ++j)
                    acc[i][j] = fmaf(a[i], b[j], acc[i][j]);
        }
        __syncthreads();
    }

    // ---- epilogue ----
    #pragma unroll
    for (int i = 0; i < TM; ++i) {
        int gm = m0 + ty * TM + i;
        if (gm >= M) continue;
        float bv = bias ? bias[(size_t)gm * bias_stride] : 0.f;
        #pragma unroll
        for (int j = 0; j < TN; ++j) {
            int gn = n0 + tx * TN + j;
            if (gn >= N) continue;
            float v = acc[i][j] + bv;
            if (Cadd) v += Cadd[(size_t)gn * ldc + gm];
            C[(size_t)gn * ldc + gm] = v;
        }
    }
}

// ---------------- launch ----------------
extern "C" void kernel_launch(void* const* d_in, const int* in_sizes, int n_in,
                              void* d_out, int out_size)
{
    const float* inputs = (const float*)d_in[0];  // (1000,1,900)
    const float* state0 = (const float*)d_in[1];  // (1,4096)
    const float* W_ih   = (const float*)d_in[2];  // (4096,900)
    const float* W_hh   = (const float*)d_in[3];  // (4096,4096)
    const float* W_out  = (const float*)d_in[4];  // (900,4997)

    float* out    = (float*)d_out;                // outputs: SEQ*IDIM
    float* states = out + (size_t)SEQ * IDIM;     // states : SEQ*HDIM

    float *U = nullptr, *P = nullptr;
    cudaGetSymbolAddress((void**)&U, g_U);
    cudaGetSymbolAddress((void**)&P, g_P);

    cudaFuncSetAttribute(esn_loop_kernel,
                         cudaFuncAttributeMaxDynamicSharedMemorySize, (int)LOOP_SMEM);

    reset_kernel<<<1, 32>>>();

    // U[t][h] = W_ih[h,:] . inp[t,:]            M=4096 N=1000 K=900
    gemm_nt<128, 128><<<dim3(HDIM / 128, (SEQ + 127) / 128), 256>>>(
        W_ih, IDIM, inputs, IDIM, U, HDIM,
        nullptr, nullptr, 0, HDIM, SEQ, IDIM);

    // P[t][i] = W_out[i][0] + W_out[i,1:901] . inp[t,:]   M=900 N=1000 K=900
    gemm_nt<64, 128><<<dim3((IDIM + 63) / 64, (SEQ + 127) / 128), 256>>>(
        W_out + 1, WOLD, inputs, IDIM, P, IDIM,
        nullptr, W_out, WOLD, IDIM, SEQ, IDIM);

    // sequential recurrence: states[t] = tanh(U[t] + W_hh @ states[t-1])
    esn_loop_kernel<<<NBLK, TPB, LOOP_SMEM>>>(W_hh, state0, states);

    // out[t][i] = P[t][i] + W_out[i,901:] . states[t,:]   M=900 N=1000 K=4096
    gemm_nt<64, 128><<<dim3((IDIM + 63) / 64, (SEQ + 127) / 128), 256>>>(
        W_out + 1 + IDIM, WOLD, states, HDIM, out, IDIM,
        P, nullptr, 0, IDIM, SEQ, HDIM);
}

// round 8
// speedup vs baseline: 1.1995x; 1.1603x over previous
#include <cuda_runtime.h>
#include <cstdint>

#define SEQ   1000
#define IDIM  900
#define HDIM  4096
#define WOLD  (HDIM + IDIM + 1)   // 4997, W_out row stride
#define NBLK  148
#define TPB   512
#define CACHE_ROWS 13
// w cache + s buffer + reduction buffer (7*2*4 floats, padded)
#define LOOP_SMEM ((CACHE_ROWS * HDIM + HDIM + 64) * sizeof(float))

typedef unsigned long long ull;

// ---------------- scratch (static device globals; no allocation) ----------------
__device__ float g_U[SEQ * HDIM];   // W_ih @ inp[t]   (t-major)
__device__ float g_P[SEQ * IDIM];   // bias + input part of readout
__device__ int   g_bar;             // monotonic arrival counter

__device__ __forceinline__ int ld_acq(const int* p) {
    int v;
    asm volatile("ld.acquire.gpu.b32 %0, [%1];" : "=r"(v) : "l"(p) : "memory");
    return v;
}
__device__ __forceinline__ void arrive_release(int* p) {
    asm volatile("red.release.gpu.global.add.s32 [%0], 1;" :: "l"(p) : "memory");
}
// packed f32x2 FMA (Blackwell FFMA2 — only reachable via PTX)
__device__ __forceinline__ ull fma2(ull a, ull b, ull c) {
    ull d;
    asm("fma.rn.f32x2 %0, %1, %2, %3;" : "=l"(d) : "l"(a), "l"(b), "l"(c));
    return d;
}
__device__ __forceinline__ float accsum(ull a) {
    return __uint_as_float((unsigned)a) + __uint_as_float((unsigned)(a >> 32));
}
__device__ __forceinline__ ull dupf(float a) {
    ull d;
    unsigned ai = __float_as_uint(a);
    asm("mov.b64 %0, {%1, %1};" : "=l"(d) : "r"(ai));
    return d;
}

__global__ void reset_kernel() {
    if (threadIdx.x == 0) g_bar = 0;
}

// ---------------- persistent recurrence kernel ----------------
// s_{t} = tanh(U[t] + W_hh @ s_{t-1});  states[t] = s_t
// 148 blocks (1/SM), 512 threads. Split-K-2: warp w (w=0..13) computes rows
// 4g..4g+3 (g=w>>1) over k-half h=w&1 with packed f32x2 FMAs; partials meet
// in SMEM, warps 0..6 combine + tanh + store. Rows 0..12 of each block's
// slice are SMEM-resident; rows 13+ stream from L2. Warp 15 polls the
// single-counter grid barrier.
__global__ __launch_bounds__(TPB, 1) void esn_loop_kernel(
    const float* __restrict__ W_hh,
    const float* __restrict__ s0,
    float* __restrict__ states)
{
    extern __shared__ float sh[];
    float* w_sh   = sh;                          // CACHE_ROWS * HDIM
    float* s_sh   = sh + CACHE_ROWS * HDIM;      // HDIM
    float* red_sh = s_sh + HDIM;                 // 7*2*4 floats

    const int bid  = blockIdx.x;
    const int tid  = threadIdx.x;
    const int warp = tid >> 5;
    const int lane = tid & 31;

    // 4096 = 148*27 + 100 -> blocks 0..99 get 28 rows, 100..147 get 27
    const int base  = bid * 27 + (bid < 100 ? bid : 100);
    const int nrows = (bid < 100) ? 28 : 27;

    // prologue: cache first CACHE_ROWS rows of this block's slice in SMEM
    {
        const float4* wsrc = (const float4*)(W_hh + (size_t)base * HDIM);
        float4* wdst = (float4*)w_sh;
        for (int i = tid; i < CACHE_ROWS * (HDIM / 4); i += TPB) wdst[i] = wsrc[i];
    }

    const int g = warp >> 1;          // row quad 0..6
    const int h = warp & 1;           // k-half
    const bool isComp = (warp < 14);
    const int kbase = h * 512;        // in 16B units (512 float4 per half)

    // per-row W pointers (t-invariant), 16B-unit indexed
    const ulonglong2* wq0 = nullptr; const ulonglong2* wq1 = nullptr;
    const ulonglong2* wq2 = nullptr; const ulonglong2* wq3 = nullptr;
    if (isComp) {
        int r[4];
        #pragma unroll
        for (int i = 0; i < 4; ++i) {
            int row = 4 * g + i;
            r[i] = row < nrows ? row : nrows - 1;   // clamp OOB reads (result discarded)
        }
        wq0 = (4*g+0 < CACHE_ROWS) ? (const ulonglong2*)(w_sh + (4*g+0) * HDIM)
                                   : (const ulonglong2*)(W_hh + (size_t)(base + r[0]) * HDIM);
        wq1 = (4*g+1 < CACHE_ROWS) ? (const ulonglong2*)(w_sh + (4*g+1) * HDIM)
                                   : (const ulonglong2*)(W_hh + (size_t)(base + r[1]) * HDIM);
        wq2 = (4*g+2 < CACHE_ROWS) ? (const ulonglong2*)(w_sh + (4*g+2) * HDIM)
                                   : (const ulonglong2*)(W_hh + (size_t)(base + r[2]) * HDIM);
        wq3 = (4*g+3 < CACHE_ROWS) ? (const ulonglong2*)(w_sh + (4*g+3) * HDIM)
                                   : (const ulonglong2*)(W_hh + (size_t)(base + r[3]) * HDIM);
    }

    const float* s_src = s0;

    for (int t = 0; t < SEQ; ++t) {
        // early, independent U load for the combine phase (hidden under compute)
        float u = 0.f;
        if (warp < 7 && lane < 4) {
            int row = 4 * warp + lane;
            int rc = row < nrows ? row : nrows - 1;
            u = g_U[(size_t)t * HDIM + base + rc];
        }

        // stage current state vector into SMEM (1024 float4, 512 threads)
        {
            const float4* src = (const float4*)s_src;
            float4* dst = (float4*)s_sh;
            float4 v0 = src[tid];
            float4 v1 = src[tid + TPB];
            dst[tid] = v0;
            dst[tid + TPB] = v1;
        }
        __syncthreads();

        if (isComp) {
            const ulonglong2* sq = (const ulonglong2*)s_sh;
            ull a0 = 0, a1 = 0, a2 = 0, a3 = 0;

            #pragma unroll
            for (int j = 0; j < 16; ++j) {
                const int idx = kbase + lane + j * 32;
                ulonglong2 s2 = sq[idx];
                ulonglong2 w0 = wq0[idx];
                ulonglong2 w1 = wq1[idx];
                ulonglong2 w2 = wq2[idx];
                ulonglong2 w3 = wq3[idx];
                a0 = fma2(w0.x, s2.x, a0); a0 = fma2(w0.y, s2.y, a0);
                a1 = fma2(w1.x, s2.x, a1); a1 = fma2(w1.y, s2.y, a1);
                a2 = fma2(w2.x, s2.x, a2); a2 = fma2(w2.y, s2.y, a2);
                a3 = fma2(w3.x, s2.x, a3); a3 = fma2(w3.y, s2.y, a3);
            }

            float r0 = accsum(a0), r1 = accsum(a1), r2 = accsum(a2), r3 = accsum(a3);
            #pragma unroll
            for (int off = 16; off; off >>= 1) {
                r0 += __shfl_xor_sync(0xffffffffu, r0, off);
                r1 += __shfl_xor_sync(0xffffffffu, r1, off);
                r2 += __shfl_xor_sync(0xffffffffu, r2, off);
                r3 += __shfl_xor_sync(0xffffffffu, r3, off);
            }
            if (lane == 0) {
                float* rp = red_sh + (g * 2 + h) * 4;
                rp[0] = r0; rp[1] = r1; rp[2] = r2; rp[3] = r3;
            }
        }
        __syncthreads();   // partials visible

        if (warp < 7 && lane < 4) {
            int row = 4 * warp + lane;
            float v = red_sh[(warp * 2 + 0) * 4 + lane]
                    + red_sh[(warp * 2 + 1) * 4 + lane];
            if (row < nrows)
                states[(size_t)t * HDIM + base + row] = tanhf(v + u);
        }
        __syncthreads();   // all states STGs of this step issued

        if (t < SEQ - 1) {
            if (tid == 0) arrive_release(&g_bar);   // release: orders the STGs
            if (warp == 15) {                       // dedicated poller warp
                const int target = (t + 1) * NBLK;
                while (ld_acq(&g_bar) < target) { }
            }
            __syncthreads();   // barrier passed; also protects s_sh reuse
        }

        s_src = states + (size_t)t * HDIM;
    }
}

// ---------------- fp32 GEMM: C[n][m] = (bias[m]) + (Cadd[n][m]) + sum_k A[m][k]*B[n][k]
// A: M x K row stride lda (scalar loads — may be unaligned base / odd lda)
// B: N x K row stride ldb (float4 when aligned)
// 256 threads, BMxBN tile, BK=8, (BM/16)x(BN/16) microtile, packed f32x2 FMAs.
template<int BM, int BN>
__global__ __launch_bounds__(256) void gemm_nt(
    const float* __restrict__ A, int lda,
    const float* __restrict__ B, int ldb,
    float* __restrict__ C, int ldc,
    const float* __restrict__ Cadd,
    const float* __restrict__ bias, int bias_stride,
    int M, int N, int K)
{
    constexpr int BK = 8;
    constexpr int TM = BM / 16;
    constexpr int TN = BN / 16;
    constexpr int TN2 = TN / 2;
    __shared__ float As[BK][BM + 4];
    __shared__ float Bs[BK][BN + 4];

    const int tid = threadIdx.x;
    const int tx = tid & 15;
    const int ty = tid >> 4;
    const int m0 = blockIdx.x * BM;
    const int n0 = blockIdx.y * BN;

    const bool b_vec = ((reinterpret_cast<uintptr_t>(B) & 15) == 0) && ((ldb & 3) == 0);

    ull acc2[TM][TN2];
    #pragma unroll
    for (int i = 0; i < TM; ++i)
        #pragma unroll
        for (int j = 0; j < TN2; ++j) acc2[i][j] = 0ull;

    for (int kt = 0; kt < K; kt += BK) {
        // ---- load A tile (BM x 8) transposed into As, scalar loads ----
        #pragma unroll
        for (int i = tid; i < BM * 2; i += 256) {
            int m = i >> 1;
            int kq = (i & 1) * 4;
            int gm = m0 + m;
            float v0 = 0.f, v1 = 0.f, v2 = 0.f, v3 = 0.f;
            if (gm < M) {
                const float* p = A + (size_t)gm * lda + (kt + kq);
                int rem = K - (kt + kq);
                if (rem > 0) v0 = p[0];
                if (rem > 1) v1 = p[1];
                if (rem > 2) v2 = p[2];
                if (rem > 3) v3 = p[3];
            }
            As[kq + 0][m] = v0; As[kq + 1][m] = v1;
            As[kq + 2][m] = v2; As[kq + 3][m] = v3;
        }
        // ---- load B tile (BN x 8) transposed into Bs ----
        #pragma unroll
        for (int i = tid; i < BN * 2; i += 256) {
            int n = i >> 1;
            int kq = (i & 1) * 4;
            int gn = n0 + n;
            int gk = kt + kq;
            float v0 = 0.f, v1 = 0.f, v2 = 0.f, v3 = 0.f;
            if (gn < N) {
                const float* p = B + (size_t)gn * ldb + gk;
                int rem = K - gk;
                if (b_vec && rem >= 4) {
                    float4 v = *(const float4*)p;
                    v0 = v.x; v1 = v.y; v2 = v.z; v3 = v.w;
                } else {
                    if (rem > 0) v0 = p[0];
                    if (rem > 1) v1 = p[1];
                    if (rem > 2) v2 = p[2];
                    if (rem > 3) v3 = p[3];
                }
            }
            Bs[kq + 0][n] = v0; Bs[kq + 1][n] = v1;
            Bs[kq + 2][n] = v2; Bs[kq + 3][n] = v3;
        }
        __syncthreads();

        #pragma unroll
        for (int kk = 0; kk < BK; ++kk) {
            ull ap[TM], b2[TN2];
            #pragma unroll
            for (int i = 0; i < TM; ++i) ap[i] = dupf(As[kk][ty * TM + i]);
            #pragma unroll
            for (int j = 0; j < TN2; ++j)
                b2[j] = *(const ull*)&Bs[kk][tx * TN + 2 * j];   // 8B-aligned
            #pragma unroll
            for (int i = 0; i < TM; ++i)
                #pragma unroll
                for (int j = 0; j < TN2; ++j)
                    acc2[i][j] = fma2(ap[i], b2[j], acc2[i][j]);
        }
        __syncthreads();
    }

    // ---- epilogue ----
    #pragma unroll
    for (int i = 0; i < TM; ++i) {
        int gm = m0 + ty * TM + i;
        if (gm >= M) continue;
        float bv = bias ? bias[(size_t)gm * bias_stride] : 0.f;
        #pragma unroll
        for (int j = 0; j < TN2; ++j) {
            float vlo = __uint_as_float((unsigned)acc2[i][j]);
            float vhi = __uint_as_float((unsigned)(acc2[i][j] >> 32));
            int gn0 = n0 + tx * TN + 2 * j;
            if (gn0 < N) {
                float v = vlo + bv;
                if (Cadd) v += Cadd[(size_t)gn0 * ldc + gm];
                C[(size_t)gn0 * ldc + gm] = v;
            }
            if (gn0 + 1 < N) {
                float v = vhi + bv;
                if (Cadd) v += Cadd[(size_t)(gn0 + 1) * ldc + gm];
                C[(size_t)(gn0 + 1) * ldc + gm] = v;
            }
        }
    }
}

// ---------------- launch ----------------
extern "C" void kernel_launch(void* const* d_in, const int* in_sizes, int n_in,
                              void* d_out, int out_size)
{
    const float* inputs = (const float*)d_in[0];  // (1000,1,900)
    const float* state0 = (const float*)d_in[1];  // (1,4096)
    const float* W_ih   = (const float*)d_in[2];  // (4096,900)
    const float* W_hh   = (const float*)d_in[3];  // (4096,4096)
    const float* W_out  = (const float*)d_in[4];  // (900,4997)

    float* out    = (float*)d_out;                // outputs: SEQ*IDIM
    float* states = out + (size_t)SEQ * IDIM;     // states : SEQ*HDIM

    float *U = nullptr, *P = nullptr;
    cudaGetSymbolAddress((void**)&U, g_U);
    cudaGetSymbolAddress((void**)&P, g_P);

    cudaFuncSetAttribute(esn_loop_kernel,
                         cudaFuncAttributeMaxDynamicSharedMemorySize, (int)LOOP_SMEM);

    reset_kernel<<<1, 32>>>();

    // U[t][h] = W_ih[h,:] . inp[t,:]            M=4096 N=1000 K=900
    gemm_nt<128, 128><<<dim3(HDIM / 128, (SEQ + 127) / 128), 256>>>(
        W_ih, IDIM, inputs, IDIM, U, HDIM,
        nullptr, nullptr, 0, HDIM, SEQ, IDIM);

    // P[t][i] = W_out[i][0] + W_out[i,1:901] . inp[t,:]   M=900 N=1000 K=900
    gemm_nt<64, 128><<<dim3((IDIM + 63) / 64, (SEQ + 127) / 128), 256>>>(
        W_out + 1, WOLD, inputs, IDIM, P, IDIM,
        nullptr, W_out, WOLD, IDIM, SEQ, IDIM);

    // sequential recurrence: states[t] = tanh(U[t] + W_hh @ states[t-1])
    esn_loop_kernel<<<NBLK, TPB, LOOP_SMEM>>>(W_hh, state0, states);

    // out[t][i] = P[t][i] + W_out[i,901:] . states[t,:]   M=900 N=1000 K=4096
    gemm_nt<64, 128><<<dim3((IDIM + 63) / 64, (SEQ + 127) / 128), 256>>>(
        W_out + 1 + IDIM, WOLD, states, HDIM, out, IDIM,
        P, nullptr, 0, IDIM, SEQ, HDIM);
}

// round 9
// speedup vs baseline: 1.2862x; 1.0724x over previous
#include <cuda_runtime.h>
#include <cstdint>

#define SEQ   1000
#define IDIM  900
#define HDIM  4096
#define WOLD  (HDIM + IDIM + 1)   // 4997, W_out row stride
#define NBLK  148
#define TPB   512
#define CACHE_ROWS 13
// w cache + s buffer + reduction buffer (7*2*4 floats, padded)
#define LOOP_SMEM ((CACHE_ROWS * HDIM + HDIM + 64) * sizeof(float))

typedef unsigned long long ull;

// ---------------- scratch (static device globals; no allocation) ----------------
__device__ float g_U[SEQ * HDIM];   // W_ih @ inp[t]   (t-major)
__device__ float g_P[SEQ * IDIM];   // bias + input part of readout
__device__ int   g_bar;             // monotonic arrival counter

__device__ __forceinline__ int ld_acq(const int* p) {
    int v;
    asm volatile("ld.acquire.gpu.b32 %0, [%1];" : "=r"(v) : "l"(p) : "memory");
    return v;
}
__device__ __forceinline__ void arrive_release(int* p) {
    asm volatile("red.release.gpu.global.add.s32 [%0], 1;" :: "l"(p) : "memory");
}
// packed f32x2 FMA (Blackwell FFMA2 — only reachable via PTX)
__device__ __forceinline__ ull fma2(ull a, ull b, ull c) {
    ull d;
    asm("fma.rn.f32x2 %0, %1, %2, %3;" : "=l"(d) : "l"(a), "l"(b), "l"(c));
    return d;
}
__device__ __forceinline__ float accsum(ull a) {
    return __uint_as_float((unsigned)a) + __uint_as_float((unsigned)(a >> 32));
}
__device__ __forceinline__ ull dupf(float a) {
    ull d;
    unsigned ai = __float_as_uint(a);
    asm("mov.b64 %0, {%1, %1};" : "=l"(d) : "r"(ai));
    return d;
}

__global__ void reset_kernel() {
    if (threadIdx.x == 0) g_bar = 0;
}

// ---------------- persistent recurrence kernel ----------------
// s_{t} = tanh(U[t] + W_hh @ s_{t-1});  states[t] = s_t
// 148 blocks (1/SM), 512 threads, split-K-2: warp w (0..13) computes rows
// 4g..4g+3 (g=w>>1) over k-half h=w&1 with packed f32x2 FMAs.
// Row 4g+3 is PERSISTENTLY cached in registers (64 regs/lane = the warp's
// k-half) -> 7 of 28 rows never transit L1. Rows 0..12 are SMEM-resident,
// the rest stream from L2. Partials combine via SMEM; warp 15 polls the
// single-counter grid barrier.
__global__ __launch_bounds__(TPB, 1) void esn_loop_kernel(
    const float* __restrict__ W_hh,
    const float* __restrict__ s0,
    float* __restrict__ states)
{
    extern __shared__ float sh[];
    float* w_sh   = sh;                          // CACHE_ROWS * HDIM
    float* s_sh   = sh + CACHE_ROWS * HDIM;      // HDIM
    float* red_sh = s_sh + HDIM;                 // 7*2*4 floats

    const int bid  = blockIdx.x;
    const int tid  = threadIdx.x;
    const int warp = tid >> 5;
    const int lane = tid & 31;

    // 4096 = 148*27 + 100 -> blocks 0..99 get 28 rows, 100..147 get 27
    const int base  = bid * 27 + (bid < 100 ? bid : 100);
    const int nrows = (bid < 100) ? 28 : 27;

    // prologue: cache first CACHE_ROWS rows of this block's slice in SMEM
    {
        const float4* wsrc = (const float4*)(W_hh + (size_t)base * HDIM);
        float4* wdst = (float4*)w_sh;
        for (int i = tid; i < CACHE_ROWS * (HDIM / 4); i += TPB) wdst[i] = wsrc[i];
    }

    const int g = warp >> 1;          // row quad 0..6
    const int h = warp & 1;           // k-half
    const bool isComp = (warp < 14);
    const int kbase = h * 512;        // in 16B units (512 float4 per half)

    // rows 4g+0..4g+2: SMEM if < CACHE_ROWS else L2 (clamped for OOB safety)
    const ulonglong2* wq0 = nullptr; const ulonglong2* wq1 = nullptr;
    const ulonglong2* wq2 = nullptr;
    // row 4g+3: persistent register cache (this warp's k-half)
    ulonglong2 wc[16];
    if (isComp) {
        int r[3];
        #pragma unroll
        for (int i = 0; i < 3; ++i) {
            int row = 4 * g + i;
            r[i] = row < nrows ? row : nrows - 1;
        }
        wq0 = (4*g+0 < CACHE_ROWS) ? (const ulonglong2*)(w_sh + (4*g+0) * HDIM)
                                   : (const ulonglong2*)(W_hh + (size_t)(base + r[0]) * HDIM);
        wq1 = (4*g+1 < CACHE_ROWS) ? (const ulonglong2*)(w_sh + (4*g+1) * HDIM)
                                   : (const ulonglong2*)(W_hh + (size_t)(base + r[1]) * HDIM);
        wq2 = (4*g+2 < CACHE_ROWS) ? (const ulonglong2*)(w_sh + (4*g+2) * HDIM)
                                   : (const ulonglong2*)(W_hh + (size_t)(base + r[2]) * HDIM);
        int rr = 4 * g + 3;
        if (rr >= nrows) rr = nrows - 1;          // clamp (result discarded)
        const ulonglong2* wrr = (const ulonglong2*)(W_hh + (size_t)(base + rr) * HDIM);
        #pragma unroll
        for (int j = 0; j < 16; ++j) wc[j] = wrr[kbase + lane + j * 32];
    }

    const float* s_src = s0;

    for (int t = 0; t < SEQ; ++t) {
        // early, independent U load for the combine phase (hidden under compute)
        float u = 0.f;
        if (warp < 7 && lane < 4) {
            int row = 4 * warp + lane;
            int rc = row < nrows ? row : nrows - 1;
            u = g_U[(size_t)t * HDIM + base + rc];
        }

        // stage current state vector into SMEM (1024 float4, 512 threads)
        {
            const float4* src = (const float4*)s_src;
            float4* dst = (float4*)s_sh;
            float4 v0 = src[tid];
            float4 v1 = src[tid + TPB];
            dst[tid] = v0;
            dst[tid + TPB] = v1;
        }
        __syncthreads();

        if (isComp) {
            const ulonglong2* sq = (const ulonglong2*)s_sh;
            ull a0 = 0, a1 = 0, a2 = 0, a3 = 0;

            #pragma unroll
            for (int j = 0; j < 16; ++j) {
                const int idx = kbase + lane + j * 32;
                ulonglong2 s2 = sq[idx];
                ulonglong2 w0 = wq0[idx];
                ulonglong2 w1 = wq1[idx];
                ulonglong2 w2 = wq2[idx];
                ulonglong2 w3 = wc[j];
                a0 = fma2(w0.x, s2.x, a0); a0 = fma2(w0.y, s2.y, a0);
                a1 = fma2(w1.x, s2.x, a1); a1 = fma2(w1.y, s2.y, a1);
                a2 = fma2(w2.x, s2.x, a2); a2 = fma2(w2.y, s2.y, a2);
                a3 = fma2(w3.x, s2.x, a3); a3 = fma2(w3.y, s2.y, a3);
            }

            float r0 = accsum(a0), r1 = accsum(a1), r2 = accsum(a2), r3 = accsum(a3);
            #pragma unroll
            for (int off = 16; off; off >>= 1) {
                r0 += __shfl_xor_sync(0xffffffffu, r0, off);
                r1 += __shfl_xor_sync(0xffffffffu, r1, off);
                r2 += __shfl_xor_sync(0xffffffffu, r2, off);
                r3 += __shfl_xor_sync(0xffffffffu, r3, off);
            }
            if (lane == 0) {
                float* rp = red_sh + (g * 2 + h) * 4;
                rp[0] = r0; rp[1] = r1; rp[2] = r2; rp[3] = r3;
            }
        }
        __syncthreads();   // partials visible

        if (warp < 7 && lane < 4) {
            int row = 4 * warp + lane;
            float v = red_sh[(warp * 2 + 0) * 4 + lane]
                    + red_sh[(warp * 2 + 1) * 4 + lane];
            if (row < nrows)
                states[(size_t)t * HDIM + base + row] = tanhf(v + u);
        }
        __syncthreads();   // all states STGs of this step issued

        if (t < SEQ - 1) {
            if (tid == 0) arrive_release(&g_bar);   // release: orders the STGs
            if (warp == 15) {                       // dedicated poller warp
                const int target = (t + 1) * NBLK;
                while (ld_acq(&g_bar) < target) { }
            }
            __syncthreads();   // barrier passed; also protects s_sh reuse
        }

        s_src = states + (size_t)t * HDIM;
    }
}

// ---------------- fp32 GEMM: C[n][m] = (bias[m]) + (Cadd[n][m]) + sum_k A[m][k]*B[n][k]
// A: M x K row stride lda (float4 when base+lda 16B-aligned, else scalar)
// B: N x K row stride ldb (float4 when aligned)
// 256 threads, BMxBN tile, BK=8, (BM/16)x(BN/16) microtile, packed f32x2 FMAs.
template<int BM, int BN>
__global__ __launch_bounds__(256) void gemm_nt(
    const float* __restrict__ A, int lda,
    const float* __restrict__ B, int ldb,
    float* __restrict__ C, int ldc,
    const float* __restrict__ Cadd,
    const float* __restrict__ bias, int bias_stride,
    int M, int N, int K)
{
    constexpr int BK = 8;
    constexpr int TM = BM / 16;
    constexpr int TN = BN / 16;
    constexpr int TN2 = TN / 2;
    __shared__ float As[BK][BM + 4];
    __shared__ float Bs[BK][BN + 4];

    const int tid = threadIdx.x;
    const int tx = tid & 15;
    const int ty = tid >> 4;
    const int m0 = blockIdx.x * BM;
    const int n0 = blockIdx.y * BN;

    const bool a_vec = ((reinterpret_cast<uintptr_t>(A) & 15) == 0) && ((lda & 3) == 0);
    const bool b_vec = ((reinterpret_cast<uintptr_t>(B) & 15) == 0) && ((ldb & 3) == 0);

    ull acc2[TM][TN2];
    #pragma unroll
    for (int i = 0; i < TM; ++i)
        #pragma unroll
        for (int j = 0; j < TN2; ++j) acc2[i][j] = 0ull;

    for (int kt = 0; kt < K; kt += BK) {
        // ---- load A tile (BM x 8) transposed into As ----
        #pragma unroll
        for (int i = tid; i < BM * 2; i += 256) {
            int m = i >> 1;
            int kq = (i & 1) * 4;
            int gm = m0 + m;
            float v0 = 0.f, v1 = 0.f, v2 = 0.f, v3 = 0.f;
            if (gm < M) {
                const float* p = A + (size_t)gm * lda + (kt + kq);
                int rem = K - (kt + kq);
                if (a_vec && rem >= 4) {
                    float4 v = *(const float4*)p;
                    v0 = v.x; v1 = v.y; v2 = v.z; v3 = v.w;
                } else {
                    if (rem > 0) v0 = p[0];
                    if (rem > 1) v1 = p[1];
                    if (rem > 2) v2 = p[2];
                    if (rem > 3) v3 = p[3];
                }
            }
            As[kq + 0][m] = v0; As[kq + 1][m] = v1;
            As[kq + 2][m] = v2; As[kq + 3][m] = v3;
        }
        // ---- load B tile (BN x 8) transposed into Bs ----
        #pragma unroll
        for (int i = tid; i < BN * 2; i += 256) {
            int n = i >> 1;
            int kq = (i & 1) * 4;
            int gn = n0 + n;
            int gk = kt + kq;
            float v0 = 0.f, v1 = 0.f, v2 = 0.f, v3 = 0.f;
            if (gn < N) {
                const float* p = B + (size_t)gn * ldb + gk;
                int rem = K - gk;
                if (b_vec && rem >= 4) {
                    float4 v = *(const float4*)p;
                    v0 = v.x; v1 = v.y; v2 = v.z; v3 = v.w;
                } else {
                    if (rem > 0) v0 = p[0];
                    if (rem > 1) v1 = p[1];
                    if (rem > 2) v2 = p[2];
                    if (rem > 3) v3 = p[3];
                }
            }
            Bs[kq + 0][n] = v0; Bs[kq + 1][n] = v1;
            Bs[kq + 2][n] = v2; Bs[kq + 3][n] = v3;
        }
        __syncthreads();

        #pragma unroll
        for (int kk = 0; kk < BK; ++kk) {
            ull ap[TM], b2[TN2];
            #pragma unroll
            for (int i = 0; i < TM; ++i) ap[i] = dupf(As[kk][ty * TM + i]);
            #pragma unroll
            for (int j = 0; j < TN2; ++j)
                b2[j] = *(const ull*)&Bs[kk][tx * TN + 2 * j];   // 8B-aligned
            #pragma unroll
            for (int i = 0; i < TM; ++i)
                #pragma unroll
                for (int j = 0; j < TN2; ++j)
                    acc2[i][j] = fma2(ap[i], b2[j], acc2[i][j]);
        }
        __syncthreads();
    }

    // ---- epilogue ----
    #pragma unroll
    for (int i = 0; i < TM; ++i) {
        int gm = m0 + ty * TM + i;
        if (gm >= M) continue;
        float bv = bias ? bias[(size_t)gm * bias_stride] : 0.f;
        #pragma unroll
        for (int j = 0; j < TN2; ++j) {
            float vlo = __uint_as_float((unsigned)acc2[i][j]);
            float vhi = __uint_as_float((unsigned)(acc2[i][j] >> 32));
            int gn0 = n0 + tx * TN + 2 * j;
            if (gn0 < N) {
                float v = vlo + bv;
                if (Cadd) v += Cadd[(size_t)gn0 * ldc + gm];
                C[(size_t)gn0 * ldc + gm] = v;
            }
            if (gn0 + 1 < N) {
                float v = vhi + bv;
                if (Cadd) v += Cadd[(size_t)(gn0 + 1) * ldc + gm];
                C[(size_t)(gn0 + 1) * ldc + gm] = v;
            }
        }
    }
}

// ---------------- launch ----------------
extern "C" void kernel_launch(void* const* d_in, const int* in_sizes, int n_in,
                              void* d_out, int out_size)
{
    const float* inputs = (const float*)d_in[0];  // (1000,1,900)
    const float* state0 = (const float*)d_in[1];  // (1,4096)
    const float* W_ih   = (const float*)d_in[2];  // (4096,900)
    const float* W_hh   = (const float*)d_in[3];  // (4096,4096)
    const float* W_out  = (const float*)d_in[4];  // (900,4997)

    float* out    = (float*)d_out;                // outputs: SEQ*IDIM
    float* states = out + (size_t)SEQ * IDIM;     // states : SEQ*HDIM

    float *U = nullptr, *P = nullptr;
    cudaGetSymbolAddress((void**)&U, g_U);
    cudaGetSymbolAddress((void**)&P, g_P);

    cudaFuncSetAttribute(esn_loop_kernel,
                         cudaFuncAttributeMaxDynamicSharedMemorySize, (int)LOOP_SMEM);

    reset_kernel<<<1, 32>>>();

    // U[t][h] = W_ih[h,:] . inp[t,:]            M=4096 N=1000 K=900
    gemm_nt<128, 128><<<dim3(HDIM / 128, (SEQ + 127) / 128), 256>>>(
        W_ih, IDIM, inputs, IDIM, U, HDIM,
        nullptr, nullptr, 0, HDIM, SEQ, IDIM);

    // P[t][i] = W_out[i][0] + W_out[i,1:901] . inp[t,:]   M=900 N=1000 K=900
    gemm_nt<64, 128><<<dim3((IDIM + 63) / 64, (SEQ + 127) / 128), 256>>>(
        W_out + 1, WOLD, inputs, IDIM, P, IDIM,
        nullptr, W_out, WOLD, IDIM, SEQ, IDIM);

    // sequential recurrence: states[t] = tanh(U[t] + W_hh @ states[t-1])
    esn_loop_kernel<<<NBLK, TPB, LOOP_SMEM>>>(W_hh, state0, states);

    // out[t][i] = P[t][i] + W_out[i,901:] . states[t,:]   M=900 N=1000 K=4096
    gemm_nt<64, 128><<<dim3((IDIM + 63) / 64, (SEQ + 127) / 128), 256>>>(
        W_out + 1 + IDIM, WOLD, states, HDIM, out, IDIM,
        P, nullptr, 0, IDIM, SEQ, HDIM);
}

// round 10
// speedup vs baseline: 1.4550x; 1.1312x over previous
#include <cuda_runtime.h>
#include <cstdint>

#define SEQ   1000
#define IDIM  900
#define HDIM  4096
#define WOLD  (HDIM + IDIM + 1)   // 4997, W_out row stride
#define NBLK  148
#define TPB   512
#define CACHE_ROWS 13
// w cache + s buffer + reduction buffer (4*28 floats, padded)
#define LOOP_SMEM ((CACHE_ROWS * HDIM + HDIM + 128) * sizeof(float))

typedef unsigned long long ull;

// ---------------- scratch (static device globals; no allocation) ----------------
__device__ float g_U[SEQ * HDIM];   // W_ih @ inp[t]   (t-major)
__device__ float g_P[SEQ * IDIM];   // bias + input part of readout
__device__ int   g_bar;             // monotonic arrival counter

__device__ __forceinline__ int ld_acq(const int* p) {
    int v;
    asm volatile("ld.acquire.gpu.b32 %0, [%1];" : "=r"(v) : "l"(p) : "memory");
    return v;
}
__device__ __forceinline__ void arrive_release(int* p) {
    asm volatile("red.release.gpu.global.add.s32 [%0], 1;" :: "l"(p) : "memory");
}
// packed f32x2 FMA (Blackwell FFMA2 — only reachable via PTX)
__device__ __forceinline__ ull fma2(ull a, ull b, ull c) {
    ull d;
    asm("fma.rn.f32x2 %0, %1, %2, %3;" : "=l"(d) : "l"(a), "l"(b), "l"(c));
    return d;
}
__device__ __forceinline__ float accsum(ull a) {
    return __uint_as_float((unsigned)a) + __uint_as_float((unsigned)(a >> 32));
}
__device__ __forceinline__ ull dupf(float a) {
    ull d;
    unsigned ai = __float_as_uint(a);
    asm("mov.b64 %0, {%1, %1};" : "=l"(d) : "r"(ai));
    return d;
}

__global__ void reset_kernel() {
    if (threadIdx.x == 0) g_bar = 0;
}

// ---------------- persistent recurrence kernel ----------------
// s_{t} = tanh(U[t] + W_hh @ s_{t-1});  states[t] = s_t
// 148 blocks (1/SM), 512 threads, split-K-4: warp w = (q, kq) with q=w>>2,
// kq=w&3 computes rows {q+4i, i=0..6} over k-quarter kq (f32x2 FMAs).
// Row-quarters i=4,5 (rows q+16, q+20 — L2-streamed rows) are PERSISTENTLY
// register-cached (64 regs/lane): 8 full rows never transit L1. Rows <13 are
// SMEM-resident, the rest stream from L2. Partials (4 per row) combine via
// SMEM in warp 0; warp 15 polls the single-counter grid barrier.
__global__ __launch_bounds__(TPB, 1) void esn_loop_kernel(
    const float* __restrict__ W_hh,
    const float* __restrict__ s0,
    float* __restrict__ states)
{
    extern __shared__ float sh[];
    float* w_sh   = sh;                          // CACHE_ROWS * HDIM
    float* s_sh   = sh + CACHE_ROWS * HDIM;      // HDIM
    float* red_sh = s_sh + HDIM;                 // 4*28 floats

    const int bid  = blockIdx.x;
    const int tid  = threadIdx.x;
    const int warp = tid >> 5;
    const int lane = tid & 31;

    // 4096 = 148*27 + 100 -> blocks 0..99 get 28 rows, 100..147 get 27
    const int base  = bid * 27 + (bid < 100 ? bid : 100);
    const int nrows = (bid < 100) ? 28 : 27;

    // prologue: cache first CACHE_ROWS rows of this block's slice in SMEM
    {
        const float4* wsrc = (const float4*)(W_hh + (size_t)base * HDIM);
        float4* wdst = (float4*)w_sh;
        for (int i = tid; i < CACHE_ROWS * (HDIM / 4); i += TPB) wdst[i] = wsrc[i];
    }

    const int q  = warp >> 2;         // row-group 0..3
    const int kq = warp & 3;          // k-quarter
    const int kbase = kq * 256;       // in 16B units (256 ulonglong2 per quarter)

    // rows i=0..3 (q,q+4,q+8,q+12): SMEM if <13 else L2; row i=6 (q+24): L2
    const ulonglong2* wp0; const ulonglong2* wp1;
    const ulonglong2* wp2; const ulonglong2* wp3; const ulonglong2* wp6;
    {
        int r0 = q,      r1 = q + 4,  r2 = q + 8;
        int r3 = q + 12; int r6 = q + 24;
        int c3 = r3 < nrows ? r3 : nrows - 1;   // r3=15 can exceed? no (15<27) — keep for safety
        int c6 = r6 < nrows ? r6 : nrows - 1;   // row 27 invalid when nrows=27
        wp0 = (const ulonglong2*)(w_sh + r0 * HDIM);
        wp1 = (const ulonglong2*)(w_sh + r1 * HDIM);
        wp2 = (const ulonglong2*)(w_sh + r2 * HDIM);
        wp3 = (r3 < CACHE_ROWS) ? (const ulonglong2*)(w_sh + r3 * HDIM)
                                : (const ulonglong2*)(W_hh + (size_t)(base + c3) * HDIM);
        wp6 = (const ulonglong2*)(W_hh + (size_t)(base + c6) * HDIM);
    }
    // persistent register cache: k-quarter of rows q+16 (i=4) and q+20 (i=5)
    ulonglong2 wc4[8], wc5[8];
    {
        const ulonglong2* p4 = (const ulonglong2*)(W_hh + (size_t)(base + q + 16) * HDIM);
        const ulonglong2* p5 = (const ulonglong2*)(W_hh + (size_t)(base + q + 20) * HDIM);
        #pragma unroll
        for (int j = 0; j < 8; ++j) {
            wc4[j] = p4[kbase + lane + j * 32];
            wc5[j] = p5[kbase + lane + j * 32];
        }
    }

    const float* s_src = s0;

    for (int t = 0; t < SEQ; ++t) {
        // early, independent U load for the combine phase (hidden under compute)
        float u = 0.f;
        if (warp == 0 && lane < 28) {
            int rc = lane < nrows ? lane : nrows - 1;
            u = g_U[(size_t)t * HDIM + base + rc];
        }

        // stage current state vector into SMEM (1024 float4, 512 threads)
        {
            const float4* src = (const float4*)s_src;
            float4* dst = (float4*)s_sh;
            float4 v0 = src[tid];
            float4 v1 = src[tid + TPB];
            dst[tid] = v0;
            dst[tid + TPB] = v1;
        }
        __syncthreads();

        {
            const ulonglong2* sq = (const ulonglong2*)s_sh;
            ull a0 = 0, a1 = 0, a2 = 0, a3 = 0, a4 = 0, a5 = 0, a6 = 0;

            #pragma unroll
            for (int j = 0; j < 8; ++j) {
                const int idx = kbase + lane + j * 32;
                ulonglong2 s2 = sq[idx];
                ulonglong2 w0 = wp0[idx];
                ulonglong2 w1 = wp1[idx];
                ulonglong2 w2 = wp2[idx];
                ulonglong2 w3 = wp3[idx];
                ulonglong2 w6 = wp6[idx];
                a0 = fma2(w0.x, s2.x, a0); a0 = fma2(w0.y, s2.y, a0);
                a1 = fma2(w1.x, s2.x, a1); a1 = fma2(w1.y, s2.y, a1);
                a2 = fma2(w2.x, s2.x, a2); a2 = fma2(w2.y, s2.y, a2);
                a3 = fma2(w3.x, s2.x, a3); a3 = fma2(w3.y, s2.y, a3);
                a4 = fma2(wc4[j].x, s2.x, a4); a4 = fma2(wc4[j].y, s2.y, a4);
                a5 = fma2(wc5[j].x, s2.x, a5); a5 = fma2(wc5[j].y, s2.y, a5);
                a6 = fma2(w6.x, s2.x, a6); a6 = fma2(w6.y, s2.y, a6);
            }

            float r0 = accsum(a0), r1 = accsum(a1), r2 = accsum(a2), r3 = accsum(a3);
            float r4 = accsum(a4), r5 = accsum(a5), r6 = accsum(a6);
            #pragma unroll
            for (int off = 16; off; off >>= 1) {
                r0 += __shfl_xor_sync(0xffffffffu, r0, off);
                r1 += __shfl_xor_sync(0xffffffffu, r1, off);
                r2 += __shfl_xor_sync(0xffffffffu, r2, off);
                r3 += __shfl_xor_sync(0xffffffffu, r3, off);
                r4 += __shfl_xor_sync(0xffffffffu, r4, off);
                r5 += __shfl_xor_sync(0xffffffffu, r5, off);
                r6 += __shfl_xor_sync(0xffffffffu, r6, off);
            }
            if (lane == 0) {
                float* rp = red_sh + kq * 28 + q;
                rp[0]  = r0; rp[4]  = r1; rp[8]  = r2; rp[12] = r3;
                rp[16] = r4; rp[20] = r5; rp[24] = r6;
            }
        }
        __syncthreads();   // partials visible

        if (warp == 0 && lane < 28) {
            float v = red_sh[lane] + red_sh[28 + lane]
                    + red_sh[56 + lane] + red_sh[84 + lane];
            if (lane < nrows)
                states[(size_t)t * HDIM + base + lane] = tanhf(v + u);
        }
        __syncthreads();   // states STGs of this step issued

        if (t < SEQ - 1) {
            if (tid == 0) arrive_release(&g_bar);   // release: orders the STGs
            if (warp == 15) {                       // poller
                const int target = (t + 1) * NBLK;
                while (ld_acq(&g_bar) < target) { }
            }
            __syncthreads();   // barrier passed; also protects s_sh reuse
        }

        s_src = states + (size_t)t * HDIM;
    }
}

// ---------------- fp32 GEMM: C[n][m] = (bias[m]) + (Cadd[n][m]) + sum_k A[m][k]*B[n][k]
// A: M x K row stride lda (float4 when aligned, else scalar)
// B: N x K row stride ldb (float4 when aligned)
// 256 threads, BMxBN tile, BK=8, (BM/16)x(BN/16) microtile, packed f32x2 FMAs.
template<int BM, int BN>
__global__ __launch_bounds__(256, 2) void gemm_nt(
    const float* __restrict__ A, int lda,
    const float* __restrict__ B, int ldb,
    float* __restrict__ C, int ldc,
    const float* __restrict__ Cadd,
    const float* __restrict__ bias, int bias_stride,
    int M, int N, int K)
{
    constexpr int BK = 8;
    constexpr int TM = BM / 16;
    constexpr int TN = BN / 16;
    constexpr int TN2 = TN / 2;
    __shared__ float As[BK][BM + 4];
    __shared__ float Bs[BK][BN + 4];

    const int tid = threadIdx.x;
    const int tx = tid & 15;
    const int ty = tid >> 4;
    const int m0 = blockIdx.x * BM;
    const int n0 = blockIdx.y * BN;

    const bool a_vec = ((reinterpret_cast<uintptr_t>(A) & 15) == 0) && ((lda & 3) == 0);
    const bool b_vec = ((reinterpret_cast<uintptr_t>(B) & 15) == 0) && ((ldb & 3) == 0);

    ull acc2[TM][TN2];
    #pragma unroll
    for (int i = 0; i < TM; ++i)
        #pragma unroll
        for (int j = 0; j < TN2; ++j) acc2[i][j] = 0ull;

    for (int kt = 0; kt < K; kt += BK) {
        // ---- load A tile (BM x 8) transposed into As ----
        #pragma unroll
        for (int i = tid; i < BM * 2; i += 256) {
            int m = i >> 1;
            int kq = (i & 1) * 4;
            int gm = m0 + m;
            float v0 = 0.f, v1 = 0.f, v2 = 0.f, v3 = 0.f;
            if (gm < M) {
                const float* p = A + (size_t)gm * lda + (kt + kq);
                int rem = K - (kt + kq);
                if (a_vec && rem >= 4) {
                    float4 v = *(const float4*)p;
                    v0 = v.x; v1 = v.y; v2 = v.z; v3 = v.w;
                } else {
                    if (rem > 0) v0 = p[0];
                    if (rem > 1) v1 = p[1];
                    if (rem > 2) v2 = p[2];
                    if (rem > 3) v3 = p[3];
                }
            }
            As[kq + 0][m] = v0; As[kq + 1][m] = v1;
            As[kq + 2][m] = v2; As[kq + 3][m] = v3;
        }
        // ---- load B tile (BN x 8) transposed into Bs ----
        #pragma unroll
        for (int i = tid; i < BN * 2; i += 256) {
            int n = i >> 1;
            int kq = (i & 1) * 4;
            int gn = n0 + n;
            int gk = kt + kq;
            float v0 = 0.f, v1 = 0.f, v2 = 0.f, v3 = 0.f;
            if (gn < N) {
                const float* p = B + (size_t)gn * ldb + gk;
                int rem = K - gk;
                if (b_vec && rem >= 4) {
                    float4 v = *(const float4*)p;
                    v0 = v.x; v1 = v.y; v2 = v.z; v3 = v.w;
                } else {
                    if (rem > 0) v0 = p[0];
                    if (rem > 1) v1 = p[1];
                    if (rem > 2) v2 = p[2];
                    if (rem > 3) v3 = p[3];
                }
            }
            Bs[kq + 0][n] = v0; Bs[kq + 1][n] = v1;
            Bs[kq + 2][n] = v2; Bs[kq + 3][n] = v3;
        }
        __syncthreads();

        #pragma unroll
        for (int kk = 0; kk < BK; ++kk) {
            ull ap[TM], b2[TN2];
            #pragma unroll
            for (int i = 0; i < TM; ++i) ap[i] = dupf(As[kk][ty * TM + i]);
            #pragma unroll
            for (int j = 0; j < TN2; ++j)
                b2[j] = *(const ull*)&Bs[kk][tx * TN + 2 * j];   // 8B-aligned
            #pragma unroll
            for (int i = 0; i < TM; ++i)
                #pragma unroll
                for (int j = 0; j < TN2; ++j)
                    acc2[i][j] = fma2(ap[i], b2[j], acc2[i][j]);
        }
        __syncthreads();
    }

    // ---- epilogue ----
    #pragma unroll
    for (int i = 0; i < TM; ++i) {
        int gm = m0 + ty * TM + i;
        if (gm >= M) continue;
        float bv = bias ? bias[(size_t)gm * bias_stride] : 0.f;
        #pragma unroll
        for (int j = 0; j < TN2; ++j) {
            float vlo = __uint_as_float((unsigned)acc2[i][j]);
            float vhi = __uint_as_float((unsigned)(acc2[i][j] >> 32));
            int gn0 = n0 + tx * TN + 2 * j;
            if (gn0 < N) {
                float v = vlo + bv;
                if (Cadd) v += Cadd[(size_t)gn0 * ldc + gm];
                C[(size_t)gn0 * ldc + gm] = v;
            }
            if (gn0 + 1 < N) {
                float v = vhi + bv;
                if (Cadd) v += Cadd[(size_t)(gn0 + 1) * ldc + gm];
                C[(size_t)(gn0 + 1) * ldc + gm] = v;
            }
        }
    }
}

// ---------------- launch ----------------
extern "C" void kernel_launch(void* const* d_in, const int* in_sizes, int n_in,
                              void* d_out, int out_size)
{
    const float* inputs = (const float*)d_in[0];  // (1000,1,900)
    const float* state0 = (const float*)d_in[1];  // (1,4096)
    const float* W_ih   = (const float*)d_in[2];  // (4096,900)
    const float* W_hh   = (const float*)d_in[3];  // (4096,4096)
    const float* W_out  = (const float*)d_in[4];  // (900,4997)

    float* out    = (float*)d_out;                // outputs: SEQ*IDIM
    float* states = out + (size_t)SEQ * IDIM;     // states : SEQ*HDIM

    float *U = nullptr, *P = nullptr;
    cudaGetSymbolAddress((void**)&U, g_U);
    cudaGetSymbolAddress((void**)&P, g_P);

    cudaFuncSetAttribute(esn_loop_kernel,
                         cudaFuncAttributeMaxDynamicSharedMemorySize, (int)LOOP_SMEM);

    reset_kernel<<<1, 32>>>();

    // U[t][h] = W_ih[h,:] . inp[t,:]            M=4096 N=1000 K=900
    gemm_nt<128, 64><<<dim3(HDIM / 128, (SEQ + 63) / 64), 256>>>(
        W_ih, IDIM, inputs, IDIM, U, HDIM,
        nullptr, nullptr, 0, HDIM, SEQ, IDIM);

    // P[t][i] = W_out[i][0] + W_out[i,1:901] . inp[t,:]   M=900 N=1000 K=900
    gemm_nt<64, 64><<<dim3((IDIM + 63) / 64, (SEQ + 63) / 64), 256>>>(
        W_out + 1, WOLD, inputs, IDIM, P, IDIM,
        nullptr, W_out, WOLD, IDIM, SEQ, IDIM);

    // sequential recurrence: states[t] = tanh(U[t] + W_hh @ states[t-1])
    esn_loop_kernel<<<NBLK, TPB, LOOP_SMEM>>>(W_hh, state0, states);

    // out[t][i] = P[t][i] + W_out[i,901:] . states[t,:]   M=900 N=1000 K=4096
    gemm_nt<64, 64><<<dim3((IDIM + 63) / 64, (SEQ + 63) / 64), 256>>>(
        W_out + 1 + IDIM, WOLD, states, HDIM, out, IDIM,
        P, nullptr, 0, IDIM, SEQ, HDIM);
}